// round 12
// baseline (speedup 1.0000x reference)
#include <cuda_runtime.h>
#include <cstdint>
#include <cstddef>

#define VIN  4096      // 16^3
#define VOUT 262144    // 64^3
#define PADF 68        // padded fp32 row stride for [o][c] tables

// ---------------- device scratch (no allocation allowed) ----------------
__device__ float g_X1[128];   // [n*64+c] sum x
__device__ float g_X2[128];   // [n*64+c] sum x^2
__device__ __align__(16) float g_WgF[64 * PADF];  // tf32-rounded Wg[o][c], padded rows
__device__ __align__(16) float g_WgT[4096];       // tf32-rounded Wg transposed [c][o]
__device__ float g_B[128];    // [n][o] fused bias
__device__ float g_rstd[2];

// ---------------- helpers ----------------
__device__ __forceinline__ uint32_t tf32_rna(float v) {
    uint32_t r;
    asm("cvt.rna.tf32.f32 %0, %1;" : "=r"(r) : "f"(v));
    return r;
}
__device__ __forceinline__ void mma_tf32(float* c, const uint32_t* a, uint32_t b0, uint32_t b1) {
    asm volatile(
        "mma.sync.aligned.m16n8k8.row.col.f32.tf32.tf32.f32 "
        "{%0,%1,%2,%3}, {%4,%5,%6,%7}, {%8,%9}, {%0,%1,%2,%3};"
        : "+f"(c[0]), "+f"(c[1]), "+f"(c[2]), "+f"(c[3])
        : "r"(a[0]), "r"(a[1]), "r"(a[2]), "r"(a[3]), "r"(b0), "r"(b1));
}
__device__ __forceinline__ void stcs2(float* p, float2 v) {
    asm volatile("st.global.cs.v2.f32 [%0], {%1, %2};" :: "l"(p), "f"(v.x), "f"(v.y) : "memory");
}
__device__ __forceinline__ void stcs4(float* p, float4 v) {
    asm volatile("st.global.cs.v4.f32 [%0], {%1, %2, %3, %4};"
                 :: "l"(p), "f"(v.x), "f"(v.y), "f"(v.z), "f"(v.w) : "memory");
}
// packed f32x2
#define FMA2(d, a, b, c_) \
    asm("fma.rn.f32x2 %0, %1, %2, %3;" : "=l"(d) : "l"(a), "l"(b), "l"(c_))
#define PACKF2(d, f) \
    asm("mov.b64 %0, {%1, %2};" : "=l"(d) : "r"(__float_as_uint(f)), "r"(__float_as_uint(f)))
#define UNPACKF2(lo, hi, v) do { \
    unsigned int _l, _h; \
    asm("mov.b64 {%0, %1}, %2;" : "=r"(_l), "=r"(_h) : "l"(v)); \
    lo = __uint_as_float(_l); hi = __uint_as_float(_h); \
} while (0)

// ---------------- kernel 1: per-(n,c) sums ----------------
__global__ void __launch_bounds__(256)
k_stats(const float* __restrict__ x) {
    const int nc = blockIdx.x;
    const float4* p = (const float4*)(x + (size_t)nc * VIN);
    float a1 = 0.f, a2 = 0.f;
#pragma unroll
    for (int i = 0; i < 4; ++i) {
        float4 v = p[threadIdx.x + i * 256];
        a1 += v.x + v.y + v.z + v.w;
        a2 += v.x * v.x + v.y * v.y + v.z * v.z + v.w * v.w;
    }
#pragma unroll
    for (int off = 16; off; off >>= 1) {
        a1 += __shfl_xor_sync(0xffffffffu, a1, off);
        a2 += __shfl_xor_sync(0xffffffffu, a2, off);
    }
    __shared__ float s1[8], s2[8];
    int wid = threadIdx.x >> 5, lid = threadIdx.x & 31;
    if (lid == 0) { s1[wid] = a1; s2[wid] = a2; }
    __syncthreads();
    if (threadIdx.x == 0) {
        float t1 = 0.f, t2 = 0.f;
        for (int w = 0; w < 8; ++w) { t1 += s1[w]; t2 += s2[w]; }
        g_X1[nc] = t1;
        g_X2[nc] = t2;
    }
}

// ---------------- kernel 2: closed-form stats + tf32 weights ----------------
__global__ void k_prep(const float* __restrict__ w_ct,
                       const float* __restrict__ b_ct,
                       const float* __restrict__ gamma,
                       const float* __restrict__ beta,
                       const float* __restrict__ w_pw) {
    __shared__ float sS1[64], sS2[64];
    __shared__ float sMean[2], sRstd[2];
    const int tid = threadIdx.x;

    if (tid < 64) {
        float s1 = 0.f, s2 = 0.f;
        for (int t = 0; t < 64; ++t) {
            float w = w_ct[tid * 64 + t];
            s1 += w;
            s2 += w * w;
        }
        sS1[tid] = s1;
        sS2[tid] = s2;
    }
    __syncthreads();

    if (tid < 2) {
        double sy = 0.0, sy2 = 0.0;
        for (int c = 0; c < 64; ++c) {
            double X1 = (double)g_X1[tid * 64 + c];
            double X2 = (double)g_X2[tid * 64 + c];
            double b  = (double)b_ct[c];
            double S1 = (double)sS1[c];
            double S2 = (double)sS2[c];
            sy  += S1 * X1 + (double)VOUT * b;
            sy2 += S2 * X2 + 2.0 * b * S1 * X1 + (double)VOUT * b * b;
        }
        double mean = sy / 16777216.0;
        double var  = sy2 / 16777216.0 - mean * mean;
        double rstd = 1.0 / sqrt(var + 1e-5);
        sMean[tid] = (float)mean;
        sRstd[tid] = (float)rstd;
        g_rstd[tid] = (float)rstd;
    }
    __syncthreads();

    // Wg[o][c] = w_pw[o,c]*gamma[c] -> tf32-rounded fp32, padded rows (pad = 0)
    for (int idx = tid; idx < 64 * PADF; idx += 256) {
        int o = idx / PADF, c = idx % PADF;
        float v = 0.f;
        if (c < 64) {
            float w = w_pw[o * 64 + c] * gamma[c];
            v = __uint_as_float(tf32_rna(w));
        }
        g_WgF[idx] = v;
    }
    // transposed copy [c][o] for the scalar pipe
    for (int idx = tid; idx < 4096; idx += 256) {
        int c = idx >> 6, o = idx & 63;
        float w = w_pw[o * 64 + c] * gamma[c];
        g_WgT[idx] = __uint_as_float(tf32_rna(w));
    }

    if (tid < 128) {
        int n = tid >> 6, o = tid & 63;
        float mean = sMean[n], rstd = sRstd[n];
        float acc1 = 0.f, acc2 = 0.f;
        for (int c = 0; c < 64; ++c) {
            float wpc = w_pw[o * 64 + c];
            acc1 += wpc * gamma[c] * (b_ct[c] - mean);
            acc2 += wpc * beta[c];
        }
        g_B[tid] = rstd * acc1 + acc2;
    }
}

// ---------------- kernel 3: dual-pipe scatter-GEMM ----------------
// Block = (n, dout, h): D[o=64][s=256], s -> (j = s>>6, wout = s&63)
// z[c][s] = w_ct[c, i, s>>6, s&3] * x[n, c, d, h, (s&63)>>2]
// out[n, o, dout, 4h + (s>>6), s&63] = rstd * D + B[n][o]
// warps 0-3: tf32 HMMA on s in [0,128).  warps 4-7: FFMA2 on s in [128,256).
__global__ void __launch_bounds__(256, 2)
k_main(const float* __restrict__ x,
       const float* __restrict__ w_ct,
       float* __restrict__ out) {
    __shared__ __align__(16) float sWg[64 * PADF];  // [o][c] tf32 bits (tensor A)
    __shared__ __align__(16) float sWgT[4096];      // [c][o] tf32 vals (scalar)
    __shared__ __align__(16) float sXT[16 * PADF];  // [w][c]
    __shared__ __align__(16) float sWT[16 * PADF];  // [jk][c] (i fixed)
    __shared__ float sB[64];

    const int tid = threadIdx.x;
    const int warp = tid >> 5;
    const int l = tid & 31;

    const int b = blockIdx.x;
    const int n = b >> 10;
    const int dout = (b >> 4) & 63;
    const int h = b & 15;
    const int d = dout >> 2, i = dout & 3;

    // ---- stage operands ----
    {
        const float4* gw = (const float4*)g_WgF;
        float4* sw = (float4*)sWg;
        for (int idx = tid; idx < 64 * PADF / 4; idx += 256)   // 1088 float4
            sw[idx] = gw[idx];
        const float4* gt = (const float4*)g_WgT;
        float4* st = (float4*)sWgT;
#pragma unroll
        for (int t = 0; t < 4; ++t)
            st[tid + t * 256] = gt[tid + t * 256];
        const int c = tid >> 2, q = tid & 3;
        float4 xv = *(const float4*)(x + (size_t)(n * 64 + c) * VIN + d * 256 + h * 16 + q * 4);
        sXT[(q * 4 + 0) * PADF + c] = xv.x;
        sXT[(q * 4 + 1) * PADF + c] = xv.y;
        sXT[(q * 4 + 2) * PADF + c] = xv.z;
        sXT[(q * 4 + 3) * PADF + c] = xv.w;
        float4 wv = *(const float4*)(w_ct + c * 64 + i * 16 + q * 4);
        sWT[(q * 4 + 0) * PADF + c] = wv.x;
        sWT[(q * 4 + 1) * PADF + c] = wv.y;
        sWT[(q * 4 + 2) * PADF + c] = wv.z;
        sWT[(q * 4 + 3) * PADF + c] = wv.w;
        if (tid < 64) sB[tid] = g_B[n * 64 + tid];
    }
    __syncthreads();

    const float rstd = g_rstd[n];
    const size_t outBase = (size_t)n * 64 * VOUT + (size_t)dout * 4096 + (size_t)h * 256;

    if (warp < 4) {
        // ================= tensor pipe: s in [0,128) =================
        const int lq = l >> 2, lr = l & 3;
        const int sBase = warp * 32;
        int xoff[4], woff[4];
#pragma unroll
        for (int nt = 0; nt < 4; ++nt) {
            int s = sBase + nt * 8 + lq;
            xoff[nt] = (((s & 63) >> 2)) * PADF;
            woff[nt] = ((s >> 6) * 4 + (s & 3)) * PADF;
        }

        float acc[4][4][4];
#pragma unroll
        for (int mt = 0; mt < 4; ++mt)
#pragma unroll
            for (int nt = 0; nt < 4; ++nt)
#pragma unroll
                for (int r = 0; r < 4; ++r) acc[mt][nt][r] = 0.f;

#pragma unroll
        for (int ks = 0; ks < 8; ++ks) {
            const int cb = ks * 8 + lr;
            uint32_t aF[4][4];
#pragma unroll
            for (int mt = 0; mt < 4; ++mt) {
                const int base = (mt * 16 + lq) * PADF + cb;
                aF[mt][0] = __float_as_uint(sWg[base]);
                aF[mt][1] = __float_as_uint(sWg[base + 8 * PADF]);
                aF[mt][2] = __float_as_uint(sWg[base + 4]);
                aF[mt][3] = __float_as_uint(sWg[base + 8 * PADF + 4]);
            }
#pragma unroll
            for (int nt = 0; nt < 4; ++nt) {
                float z0 = sXT[xoff[nt] + cb] * sWT[woff[nt] + cb];
                float z1 = sXT[xoff[nt] + cb + 4] * sWT[woff[nt] + cb + 4];
                uint32_t b0 = tf32_rna(z0);
                uint32_t b1 = tf32_rna(z1);
#pragma unroll
                for (int mt = 0; mt < 4; ++mt)
                    mma_tf32(acc[mt][nt], aF[mt], b0, b1);
            }
        }

#pragma unroll
        for (int mt = 0; mt < 4; ++mt) {
            const int o0 = mt * 16 + lq;
            const int o1 = o0 + 8;
            const float B0 = sB[o0], B1 = sB[o1];
            float* p0 = out + outBase + (size_t)o0 * VOUT;
            float* p1 = out + outBase + (size_t)o1 * VOUT;
#pragma unroll
            for (int nt = 0; nt < 4; ++nt) {
                const int s = sBase + nt * 8 + 2 * lr;
                float2 v0, v1;
                v0.x = fmaf(rstd, acc[mt][nt][0], B0);
                v0.y = fmaf(rstd, acc[mt][nt][1], B0);
                v1.x = fmaf(rstd, acc[mt][nt][2], B1);
                v1.y = fmaf(rstd, acc[mt][nt][3], B1);
                stcs2(p0 + s, v0);
                stcs2(p1 + s, v1);
            }
        }
    } else {
        // ================= scalar FFMA2 pipe: s in [128,256) =================
        const int wq = warp - 4;                 // 0..3
        const int j = 2 + (wq >> 1);             // s>>6
        const int sbase = 128 + wq * 32;
        const int sgrp = l & 7;                  // s-quad within slab
        const int w_in = (wq & 1) * 8 + sgrp;    // input w index
        const int ob = (l >> 3) * 16;            // 16-o group

        unsigned long long acc[8][4];
#pragma unroll
        for (int p = 0; p < 8; ++p)
#pragma unroll
            for (int k = 0; k < 4; ++k) acc[p][k] = 0ULL;

        const float* xrow = sXT + w_in * PADF;
        const float* wr0 = sWT + (j * 4 + 0) * PADF;
        const float* wr1 = sWT + (j * 4 + 1) * PADF;
        const float* wr2 = sWT + (j * 4 + 2) * PADF;
        const float* wr3 = sWT + (j * 4 + 3) * PADF;

#pragma unroll 2
        for (int c = 0; c < 64; ++c) {
            const float xv = xrow[c];
            float t0 = xv * wr0[c], t1 = xv * wr1[c];
            float t2 = xv * wr2[c], t3 = xv * wr3[c];
            unsigned long long tt0, tt1, tt2, tt3;
            PACKF2(tt0, t0);
            PACKF2(tt1, t1);
            PACKF2(tt2, t2);
            PACKF2(tt3, t3);

            const ulonglong2* wg = (const ulonglong2*)&sWgT[c * 64 + ob];
            ulonglong2 w01 = wg[0], w23 = wg[1], w45 = wg[2], w67 = wg[3];
            unsigned long long wp0 = w01.x, wp1 = w01.y, wp2 = w23.x, wp3 = w23.y;
            unsigned long long wp4 = w45.x, wp5 = w45.y, wp6 = w67.x, wp7 = w67.y;

#define STEP(p, wpr)                          \
            FMA2(acc[p][0], wpr, tt0, acc[p][0]); \
            FMA2(acc[p][1], wpr, tt1, acc[p][1]); \
            FMA2(acc[p][2], wpr, tt2, acc[p][2]); \
            FMA2(acc[p][3], wpr, tt3, acc[p][3]);
            STEP(0, wp0) STEP(1, wp1) STEP(2, wp2) STEP(3, wp3)
            STEP(4, wp4) STEP(5, wp5) STEP(6, wp6) STEP(7, wp7)
#undef STEP
        }

        // epilogue: s0 = sbase + sgrp*4, 4 consecutive s per float4
        const int s0 = sbase + sgrp * 4;
#pragma unroll
        for (int p = 0; p < 8; ++p) {
            float lo0, hi0, lo1, hi1, lo2, hi2, lo3, hi3;
            UNPACKF2(lo0, hi0, acc[p][0]);
            UNPACKF2(lo1, hi1, acc[p][1]);
            UNPACKF2(lo2, hi2, acc[p][2]);
            UNPACKF2(lo3, hi3, acc[p][3]);
            const int o0 = ob + 2 * p;
            const int o1 = o0 + 1;
            const float B0 = sB[o0], B1 = sB[o1];
            float4 r0, r1;
            r0.x = fmaf(rstd, lo0, B0);
            r0.y = fmaf(rstd, lo1, B0);
            r0.z = fmaf(rstd, lo2, B0);
            r0.w = fmaf(rstd, lo3, B0);
            r1.x = fmaf(rstd, hi0, B1);
            r1.y = fmaf(rstd, hi1, B1);
            r1.z = fmaf(rstd, hi2, B1);
            r1.w = fmaf(rstd, hi3, B1);
            stcs4(out + outBase + (size_t)o0 * VOUT + s0, r0);
            stcs4(out + outBase + (size_t)o1 * VOUT + s0, r1);
        }
    }
}

extern "C" void kernel_launch(void* const* d_in, const int* in_sizes, int n_in,
                              void* d_out, int out_size) {
    (void)in_sizes; (void)n_in; (void)out_size;
    const float* x     = (const float*)d_in[0];
    const float* w_ct  = (const float*)d_in[1];
    const float* b_ct  = (const float*)d_in[2];
    const float* gamma = (const float*)d_in[3];
    const float* beta  = (const float*)d_in[4];
    const float* w_pw  = (const float*)d_in[5];
    float* out = (float*)d_out;

    k_stats<<<128, 256>>>(x);
    k_prep<<<1, 256>>>(w_ct, b_ct, gamma, beta, w_pw);
    k_main<<<2048, 256>>>(x, w_ct, out);
}

// round 13
// speedup vs baseline: 1.6080x; 1.6080x over previous
#include <cuda_runtime.h>
#include <cstdint>
#include <cstddef>

#define VIN  4096      // 16^3
#define VOUT 262144    // 64^3
#define PADF 68        // padded fp32 row stride (68 mod 32 = 4 -> conflict-free frags)

// ---------------- device scratch (no allocation allowed) ----------------
__device__ float g_P1[512];   // partial sums: [nc*4+q]
__device__ float g_P2[512];
__device__ __align__(16) float g_WgF[64 * PADF];  // tf32-rounded Wg[o][c], padded rows
__device__ float g_B[128];    // [n][o] fused bias
__device__ float g_rstd[2];

// ---------------- helpers ----------------
__device__ __forceinline__ uint32_t tf32_rna(float v) {
    uint32_t r;
    asm("cvt.rna.tf32.f32 %0, %1;" : "=r"(r) : "f"(v));
    return r;
}
__device__ __forceinline__ void mma_tf32(float* c, const uint32_t* a, uint32_t b0, uint32_t b1) {
    asm volatile(
        "mma.sync.aligned.m16n8k8.row.col.f32.tf32.tf32.f32 "
        "{%0,%1,%2,%3}, {%4,%5,%6,%7}, {%8,%9}, {%0,%1,%2,%3};"
        : "+f"(c[0]), "+f"(c[1]), "+f"(c[2]), "+f"(c[3])
        : "r"(a[0]), "r"(a[1]), "r"(a[2]), "r"(a[3]), "r"(b0), "r"(b1));
}
__device__ __forceinline__ void stcs2(float* p, float2 v) {
    asm volatile("st.global.cs.v2.f32 [%0], {%1, %2};" :: "l"(p), "f"(v.x), "f"(v.y) : "memory");
}

// ---------------- kernel 0: dummy (ncu launch-index alignment) ----------------
__global__ void k_nop() {}

// ---------------- kernel 1: per-(n,c,quarter) partial sums ----------------
// 512 blocks x 256 threads, 1 float4 per thread (1024 floats per block)
__global__ void __launch_bounds__(256)
k_stats(const float* __restrict__ x) {
    const int b = blockIdx.x;          // nc*4 + q
    const float4* p = (const float4*)(x + (size_t)b * 1024);
    float4 v = p[threadIdx.x];
    float a1 = v.x + v.y + v.z + v.w;
    float a2 = v.x * v.x + v.y * v.y + v.z * v.z + v.w * v.w;
#pragma unroll
    for (int off = 16; off; off >>= 1) {
        a1 += __shfl_xor_sync(0xffffffffu, a1, off);
        a2 += __shfl_xor_sync(0xffffffffu, a2, off);
    }
    __shared__ float s1[8], s2[8];
    int wid = threadIdx.x >> 5, lid = threadIdx.x & 31;
    if (lid == 0) { s1[wid] = a1; s2[wid] = a2; }
    __syncthreads();
    if (threadIdx.x == 0) {
        float t1 = 0.f, t2 = 0.f;
#pragma unroll
        for (int w = 0; w < 8; ++w) { t1 += s1[w]; t2 += s2[w]; }
        g_P1[b] = t1;
        g_P2[b] = t2;
    }
}

// ---------------- kernel 2: closed-form stats + tf32 weights ----------------
__global__ void k_prep(const float* __restrict__ w_ct,
                       const float* __restrict__ b_ct,
                       const float* __restrict__ gamma,
                       const float* __restrict__ beta,
                       const float* __restrict__ w_pw) {
    __shared__ double dS1[128], dS2[128];   // per-(n,c) contribution terms
    __shared__ float sMean[2], sRstd[2];
    const int tid = threadIdx.x;

    // per-(n,c): weight sums + closed-form contributions to sum(y), sum(y^2), in fp64
    if (tid < 128) {
        const int c = tid & 63;
        float s1 = 0.f, s2 = 0.f;
#pragma unroll 4
        for (int t = 0; t < 64; ++t) {
            float w = w_ct[c * 64 + t];
            s1 += w;
            s2 += w * w;
        }
        float X1 = g_P1[tid * 4] + g_P1[tid * 4 + 1] + g_P1[tid * 4 + 2] + g_P1[tid * 4 + 3];
        float X2 = g_P2[tid * 4] + g_P2[tid * 4 + 1] + g_P2[tid * 4 + 2] + g_P2[tid * 4 + 3];
        double bb = (double)b_ct[c];
        double S1 = (double)s1, S2 = (double)s2;
        dS1[tid] = S1 * (double)X1 + (double)VOUT * bb;
        dS2[tid] = S2 * (double)X2 + 2.0 * bb * S1 * (double)X1 + (double)VOUT * bb * bb;
    }
    __syncthreads();
    // tree-reduce 64 doubles per n (stride within each n's half)
#pragma unroll
    for (int st = 32; st > 0; st >>= 1) {
        if ((tid & 63) < st && tid < 128) {
            dS1[tid] += dS1[tid + st];
            dS2[tid] += dS2[tid + st];
        }
        __syncthreads();
    }
    if (tid < 2) {
        double sy = dS1[tid * 64], sy2 = dS2[tid * 64];
        double mean = sy / 16777216.0;
        double var  = sy2 / 16777216.0 - mean * mean;
        double rstd = 1.0 / sqrt(var + 1e-5);
        sMean[tid] = (float)mean;
        sRstd[tid] = (float)rstd;
        g_rstd[tid] = (float)rstd;
    }
    __syncthreads();

    // Wg[o][c] = w_pw[o,c]*gamma[c] -> tf32-rounded fp32, padded rows (pad = 0)
    for (int idx = tid; idx < 64 * PADF; idx += 256) {
        int o = idx / PADF, c = idx % PADF;
        float v = 0.f;
        if (c < 64) {
            float w = w_pw[o * 64 + c] * gamma[c];
            v = __uint_as_float(tf32_rna(w));
        }
        g_WgF[idx] = v;
    }

    if (tid < 128) {
        int n = tid >> 6, o = tid & 63;
        float mean = sMean[n], rstd = sRstd[n];
        float acc1 = 0.f, acc2 = 0.f;
#pragma unroll 4
        for (int c = 0; c < 64; ++c) {
            float wpc = w_pw[o * 64 + c];
            acc1 += wpc * gamma[c] * (b_ct[c] - mean);
            acc2 += wpc * beta[c];
        }
        g_B[tid] = rstd * acc1 + acc2;
    }
}

// ---------------- kernel 3: tf32 HMMA scatter-GEMM (64o x 128s tiles) ----------------
// Block = (n, dout, h, T): D[o=64][s=128T..128T+127], s indexes (j = s>>6, wout = s&63)
// z[c][s] = w_ct[c, i, s>>6, s&3] * x[n, c, d, h, (s&63)>>2]
// out[n, o, dout, 4h + (s>>6), s&63] = rstd * D + B[n][o]
__global__ void __launch_bounds__(128, 4)
k_main(const float* __restrict__ x,
       const float* __restrict__ w_ct,
       float* __restrict__ out) {
    __shared__ __align__(16) float sWg[64 * PADF];  // [o][c] tf32 bits
    __shared__ __align__(16) float sXT[16 * PADF];  // [w][c]
    __shared__ __align__(16) float sWT[16 * PADF];  // [jk][c] (i fixed)
    __shared__ float sB[64];

    const int tid = threadIdx.x;
    const int warp = tid >> 5;
    const int l = tid & 31;
    const int lq = l >> 2, lr = l & 3;

    const int b = blockIdx.x;
    const int n = b >> 11;
    const int dout = (b >> 5) & 63;
    const int h = (b >> 1) & 15;
    const int T = b & 1;
    const int d = dout >> 2, i = dout & 3;

    // ---- stage operands ----
    {
        const float4* gw = (const float4*)g_WgF;
        float4* sw = (float4*)sWg;
        for (int idx = tid; idx < 64 * PADF / 4; idx += 128)   // 1088 float4
            sw[idx] = gw[idx];
        for (int idx = tid; idx < 256; idx += 128) {
            const int c = idx >> 2, q = idx & 3;
            float4 xv = *(const float4*)(x + (size_t)(n * 64 + c) * VIN + d * 256 + h * 16 + q * 4);
            sXT[(q * 4 + 0) * PADF + c] = xv.x;
            sXT[(q * 4 + 1) * PADF + c] = xv.y;
            sXT[(q * 4 + 2) * PADF + c] = xv.z;
            sXT[(q * 4 + 3) * PADF + c] = xv.w;
            float4 wv = *(const float4*)(w_ct + c * 64 + i * 16 + q * 4);
            sWT[(q * 4 + 0) * PADF + c] = wv.x;
            sWT[(q * 4 + 1) * PADF + c] = wv.y;
            sWT[(q * 4 + 2) * PADF + c] = wv.z;
            sWT[(q * 4 + 3) * PADF + c] = wv.w;
        }
        if (tid < 64) sB[tid] = g_B[n * 64 + tid];
    }
    __syncthreads();

    const float rstd = g_rstd[n];

    // per-warp column slab: s = sBase + nt*8 + lq
    const int sBase = T * 128 + warp * 32;
    int xoff[4], woff[4];
#pragma unroll
    for (int nt = 0; nt < 4; ++nt) {
        int s = sBase + nt * 8 + lq;
        xoff[nt] = (((s & 63) >> 2)) * PADF;
        woff[nt] = ((s >> 6) * 4 + (s & 3)) * PADF;
    }

    float acc[4][4][4];
#pragma unroll
    for (int mt = 0; mt < 4; ++mt)
#pragma unroll
        for (int nt = 0; nt < 4; ++nt)
#pragma unroll
            for (int r = 0; r < 4; ++r) acc[mt][nt][r] = 0.f;

#pragma unroll
    for (int ks = 0; ks < 8; ++ks) {
        const int cb = ks * 8 + lr;
        // A fragments: a0 = Wg[mt*16+lq][cb], a1 = +8 rows, a2 = +4 cols, a3 = both
        uint32_t aF[4][4];
#pragma unroll
        for (int mt = 0; mt < 4; ++mt) {
            const int base = (mt * 16 + lq) * PADF + cb;
            aF[mt][0] = __float_as_uint(sWg[base]);
            aF[mt][1] = __float_as_uint(sWg[base + 8 * PADF]);
            aF[mt][2] = __float_as_uint(sWg[base + 4]);
            aF[mt][3] = __float_as_uint(sWg[base + 8 * PADF + 4]);
        }
#pragma unroll
        for (int nt = 0; nt < 4; ++nt) {
            float z0 = sXT[xoff[nt] + cb] * sWT[woff[nt] + cb];
            float z1 = sXT[xoff[nt] + cb + 4] * sWT[woff[nt] + cb + 4];
            uint32_t b0 = tf32_rna(z0);
            uint32_t b1 = tf32_rna(z1);
#pragma unroll
            for (int mt = 0; mt < 4; ++mt)
                mma_tf32(acc[mt][nt], aF[mt], b0, b1);
        }
    }

    // ---- epilogue: rstd scale + fused bias, coalesced streaming float2 stores ----
    const size_t outBase = (size_t)n * 64 * VOUT + (size_t)dout * 4096 + (size_t)h * 256;
#pragma unroll
    for (int mt = 0; mt < 4; ++mt) {
        const int o0 = mt * 16 + lq;
        const int o1 = o0 + 8;
        const float B0 = sB[o0], B1 = sB[o1];
        float* p0 = out + outBase + (size_t)o0 * VOUT;
        float* p1 = out + outBase + (size_t)o1 * VOUT;
#pragma unroll
        for (int nt = 0; nt < 4; ++nt) {
            const int s = sBase + nt * 8 + 2 * lr;
            float2 v0, v1;
            v0.x = fmaf(rstd, acc[mt][nt][0], B0);
            v0.y = fmaf(rstd, acc[mt][nt][1], B0);
            v1.x = fmaf(rstd, acc[mt][nt][2], B1);
            v1.y = fmaf(rstd, acc[mt][nt][3], B1);
            stcs2(p0 + s, v0);
            stcs2(p1 + s, v1);
        }
    }
}

extern "C" void kernel_launch(void* const* d_in, const int* in_sizes, int n_in,
                              void* d_out, int out_size) {
    (void)in_sizes; (void)n_in; (void)out_size;
    const float* x     = (const float*)d_in[0];
    const float* w_ct  = (const float*)d_in[1];
    const float* b_ct  = (const float*)d_in[2];
    const float* gamma = (const float*)d_in[3];
    const float* beta  = (const float*)d_in[4];
    const float* w_pw  = (const float*)d_in[5];
    float* out = (float*)d_out;

    k_stats<<<512, 256>>>(x);
    k_prep<<<1, 256>>>(w_ct, b_ct, gamma, beta, w_pw);
    k_nop<<<1, 32>>>();               // aligns ncu -s 5 onto k_main
    k_main<<<4096, 128>>>(x, w_ct, out);
}

// round 14
// speedup vs baseline: 1.8776x; 1.1676x over previous
#include <cuda_runtime.h>
#include <cstdint>
#include <cstddef>

#define VIN  4096      // 16^3
#define VOUT 262144    // 64^3
#define PADP 34        // float2 row stride for paired x/w tables (16 rows x 32 pairs + pad)

// ---------------- device scratch (no allocation allowed) ----------------
__device__ float g_P1[512];   // partial sums: [nc*4+q]
__device__ float g_P2[512];
__device__ __align__(16) uint4 g_Frag[1024];   // [ks][mt][lane] A-fragments (tf32 bits), 16KB
__device__ float g_B[128];    // [n][o] fused bias
__device__ float g_rstd[2];

// ---------------- helpers ----------------
__device__ __forceinline__ uint32_t tf32_rna(float v) {
    uint32_t r;
    asm("cvt.rna.tf32.f32 %0, %1;" : "=r"(r) : "f"(v));
    return r;
}
__device__ __forceinline__ void mma_tf32(float* c, const uint32_t* a, uint32_t b0, uint32_t b1) {
    asm volatile(
        "mma.sync.aligned.m16n8k8.row.col.f32.tf32.tf32.f32 "
        "{%0,%1,%2,%3}, {%4,%5,%6,%7}, {%8,%9}, {%0,%1,%2,%3};"
        : "+f"(c[0]), "+f"(c[1]), "+f"(c[2]), "+f"(c[3])
        : "r"(a[0]), "r"(a[1]), "r"(a[2]), "r"(a[3]), "r"(b0), "r"(b1));
}
__device__ __forceinline__ void stcs2(float* p, float2 v) {
    asm volatile("st.global.cs.v2.f32 [%0], {%1, %2};" :: "l"(p), "f"(v.x), "f"(v.y) : "memory");
}

// ---------------- kernel 0: dummy (ncu launch-index alignment) ----------------
__global__ void k_nop() {}

// ---------------- kernel 1: per-(n,c,quarter) partial sums ----------------
__global__ void __launch_bounds__(256)
k_stats(const float* __restrict__ x) {
    const int b = blockIdx.x;          // nc*4 + q
    const float4* p = (const float4*)(x + (size_t)b * 1024);
    float4 v = p[threadIdx.x];
    float a1 = v.x + v.y + v.z + v.w;
    float a2 = v.x * v.x + v.y * v.y + v.z * v.z + v.w * v.w;
#pragma unroll
    for (int off = 16; off; off >>= 1) {
        a1 += __shfl_xor_sync(0xffffffffu, a1, off);
        a2 += __shfl_xor_sync(0xffffffffu, a2, off);
    }
    __shared__ float s1[8], s2[8];
    int wid = threadIdx.x >> 5, lid = threadIdx.x & 31;
    if (lid == 0) { s1[wid] = a1; s2[wid] = a2; }
    __syncthreads();
    if (threadIdx.x == 0) {
        float t1 = 0.f, t2 = 0.f;
#pragma unroll
        for (int w = 0; w < 8; ++w) { t1 += s1[w]; t2 += s2[w]; }
        g_P1[b] = t1;
        g_P2[b] = t2;
    }
}

// ---------------- kernel 2: closed-form stats + fragment-ordered tf32 weights ----------------
__global__ void k_prep(const float* __restrict__ w_ct,
                       const float* __restrict__ b_ct,
                       const float* __restrict__ gamma,
                       const float* __restrict__ beta,
                       const float* __restrict__ w_pw) {
    __shared__ double dS1[128], dS2[128];
    __shared__ float sMean[2], sRstd[2];
    const int tid = threadIdx.x;

    if (tid < 128) {
        const int c = tid & 63;
        float s1 = 0.f, s2 = 0.f;
#pragma unroll 4
        for (int t = 0; t < 64; ++t) {
            float w = w_ct[c * 64 + t];
            s1 += w;
            s2 += w * w;
        }
        float X1 = g_P1[tid * 4] + g_P1[tid * 4 + 1] + g_P1[tid * 4 + 2] + g_P1[tid * 4 + 3];
        float X2 = g_P2[tid * 4] + g_P2[tid * 4 + 1] + g_P2[tid * 4 + 2] + g_P2[tid * 4 + 3];
        double bb = (double)b_ct[c];
        double S1 = (double)s1, S2 = (double)s2;
        dS1[tid] = S1 * (double)X1 + (double)VOUT * bb;
        dS2[tid] = S2 * (double)X2 + 2.0 * bb * S1 * (double)X1 + (double)VOUT * bb * bb;
    }
    __syncthreads();
#pragma unroll
    for (int st = 32; st > 0; st >>= 1) {
        if ((tid & 63) < st && tid < 128) {
            dS1[tid] += dS1[tid + st];
            dS2[tid] += dS2[tid + st];
        }
        __syncthreads();
    }
    if (tid < 2) {
        double sy = dS1[tid * 64], sy2 = dS2[tid * 64];
        double mean = sy / 16777216.0;
        double var  = sy2 / 16777216.0 - mean * mean;
        double rstd = 1.0 / sqrt(var + 1e-5);
        sMean[tid] = (float)mean;
        sRstd[tid] = (float)rstd;
        g_rstd[tid] = (float)rstd;
    }
    __syncthreads();

    // Fragment-ordered A: g_Frag[ks][mt][lane] = {Wg[mt*16+lq][ks*8+lr],
    //   Wg[mt*16+8+lq][ks*8+lr], Wg[mt*16+lq][ks*8+lr+4], Wg[mt*16+8+lq][ks*8+lr+4]}
    // with Wg[o][c] = tf32(w_pw[o,c] * gamma[c]).
    for (int idx = tid; idx < 1024; idx += 256) {
        const int ks = idx >> 7;
        const int mt = (idx >> 5) & 3;
        const int l = idx & 31;
        const int lq = l >> 2, lr = l & 3;
        const int o0 = mt * 16 + lq, o1 = o0 + 8;
        const int c0 = ks * 8 + lr, c1 = c0 + 4;
        uint4 f;
        f.x = tf32_rna(w_pw[o0 * 64 + c0] * gamma[c0]);
        f.y = tf32_rna(w_pw[o1 * 64 + c0] * gamma[c0]);
        f.z = tf32_rna(w_pw[o0 * 64 + c1] * gamma[c1]);
        f.w = tf32_rna(w_pw[o1 * 64 + c1] * gamma[c1]);
        g_Frag[idx] = f;
    }

    if (tid < 128) {
        int n = tid >> 6, o = tid & 63;
        float mean = sMean[n], rstd = sRstd[n];
        float acc1 = 0.f, acc2 = 0.f;
#pragma unroll 4
        for (int c = 0; c < 64; ++c) {
            float wpc = w_pw[o * 64 + c];
            acc1 += wpc * gamma[c] * (b_ct[c] - mean);
            acc2 += wpc * beta[c];
        }
        g_B[tid] = rstd * acc1 + acc2;
    }
}

// ---------------- kernel 3: tf32 HMMA scatter-GEMM, vectorized-operand mainloop ----------------
// Block = (n, dout, h, T): D[o=64][s in 128T..128T+127]
// z[c][s] = w_ct[c, i, s>>6, s&3] * x[n, c, d, h, (s&63)>>2]
// out[n, o, dout, 4h + (s>>6), s&63] = rstd * D + B[n][o]
__global__ void __launch_bounds__(128, 4)
k_main(const float* __restrict__ x,
       const float* __restrict__ w_ct,
       float* __restrict__ out) {
    __shared__ __align__(16) uint4 sFrag[1024];            // A fragments, 16 KB
    __shared__ __align__(16) float2 sXp[16 * PADP];        // [w][pair p] (x[c], x[c+4])
    __shared__ __align__(16) float2 sWp[16 * PADP];        // [jk][pair p]
    __shared__ float sB[64];

    const int tid = threadIdx.x;
    const int warp = tid >> 5;
    const int l = tid & 31;
    const int lq = l >> 2, lr = l & 3;

    const int b = blockIdx.x;
    const int n = b >> 11;
    const int dout = (b >> 5) & 63;
    const int h = (b >> 1) & 15;
    const int T = b & 1;
    const int d = dout >> 2, i = dout & 3;

    // ---- stage operands ----
    {
#pragma unroll
        for (int t = 0; t < 8; ++t)
            sFrag[tid + t * 128] = g_Frag[tid + t * 128];
        // x and w_ct slices into paired layout: pair p(c) = (c>>3)*4 + (c&3),
        // component t(c) = (c>>2)&1. c = ks*8 + lr (+4).
        float* xp = (float*)sXp;
        float* wp = (float*)sWp;
#pragma unroll
        for (int idx = tid; idx < 256; idx += 128) {
            const int c = idx >> 2, q = idx & 3;
            const int p2 = ((c >> 3) * 4 + (c & 3)) * 2 + ((c >> 2) & 1);  // float idx in row
            float4 xv = *(const float4*)(x + (size_t)(n * 64 + c) * VIN + d * 256 + h * 16 + q * 4);
            xp[(q * 4 + 0) * (2 * PADP) + p2] = xv.x;
            xp[(q * 4 + 1) * (2 * PADP) + p2] = xv.y;
            xp[(q * 4 + 2) * (2 * PADP) + p2] = xv.z;
            xp[(q * 4 + 3) * (2 * PADP) + p2] = xv.w;
            float4 wv = *(const float4*)(w_ct + c * 64 + i * 16 + q * 4);
            wp[(q * 4 + 0) * (2 * PADP) + p2] = wv.x;
            wp[(q * 4 + 1) * (2 * PADP) + p2] = wv.y;
            wp[(q * 4 + 2) * (2 * PADP) + p2] = wv.z;
            wp[(q * 4 + 3) * (2 * PADP) + p2] = wv.w;
        }
        if (tid < 64) sB[tid] = g_B[n * 64 + tid];
    }
    __syncthreads();

    const float rstd = g_rstd[n];

    // per-warp column slab: s = sBase + nt*8 + lq (lq = mma n-col)
    const int sBase = T * 128 + warp * 32;
    int xrow[4], wrow[4];
#pragma unroll
    for (int nt = 0; nt < 4; ++nt) {
        int s = sBase + nt * 8 + lq;
        xrow[nt] = ((s & 63) >> 2) * PADP;
        wrow[nt] = ((s >> 6) * 4 + (s & 3)) * PADP;
    }

    float acc[4][4][4];
#pragma unroll
    for (int mt = 0; mt < 4; ++mt)
#pragma unroll
        for (int nt = 0; nt < 4; ++nt)
#pragma unroll
            for (int r = 0; r < 4; ++r) acc[mt][nt][r] = 0.f;

#pragma unroll
    for (int ks = 0; ks < 8; ++ks) {
        // A fragments: one LDS.128 per mt, coalesced (lane-ordered layout)
        uint4 aV[4];
#pragma unroll
        for (int mt = 0; mt < 4; ++mt)
            aV[mt] = sFrag[(ks * 4 + mt) * 32 + l];
        const int p = ks * 4 + lr;
#pragma unroll
        for (int nt = 0; nt < 4; ++nt) {
            float2 xv = sXp[xrow[nt] + p];
            float2 wv = sWp[wrow[nt] + p];
            uint32_t b0 = tf32_rna(xv.x * wv.x);
            uint32_t b1 = tf32_rna(xv.y * wv.y);
#pragma unroll
            for (int mt = 0; mt < 4; ++mt)
                mma_tf32(acc[mt][nt], (const uint32_t*)&aV[mt], b0, b1);
        }
    }

    // ---- epilogue: rstd scale + fused bias, streaming float2 stores ----
    const size_t outBase = (size_t)n * 64 * VOUT + (size_t)dout * 4096 + (size_t)h * 256;
#pragma unroll
    for (int mt = 0; mt < 4; ++mt) {
        const int o0 = mt * 16 + lq;
        const int o1 = o0 + 8;
        const float B0 = sB[o0], B1 = sB[o1];
        float* p0 = out + outBase + (size_t)o0 * VOUT;
        float* p1 = out + outBase + (size_t)o1 * VOUT;
#pragma unroll
        for (int nt = 0; nt < 4; ++nt) {
            const int s = sBase + nt * 8 + 2 * lr;
            float2 v0, v1;
            v0.x = fmaf(rstd, acc[mt][nt][0], B0);
            v0.y = fmaf(rstd, acc[mt][nt][1], B0);
            v1.x = fmaf(rstd, acc[mt][nt][2], B1);
            v1.y = fmaf(rstd, acc[mt][nt][3], B1);
            stcs2(p0 + s, v0);
            stcs2(p1 + s, v1);
        }
    }
}

extern "C" void kernel_launch(void* const* d_in, const int* in_sizes, int n_in,
                              void* d_out, int out_size) {
    (void)in_sizes; (void)n_in; (void)out_size;
    const float* x     = (const float*)d_in[0];
    const float* w_ct  = (const float*)d_in[1];
    const float* b_ct  = (const float*)d_in[2];
    const float* gamma = (const float*)d_in[3];
    const float* beta  = (const float*)d_in[4];
    const float* w_pw  = (const float*)d_in[5];
    float* out = (float*)d_out;

    k_stats<<<512, 256>>>(x);
    k_prep<<<1, 256>>>(w_ct, b_ct, gamma, beta, w_pw);
    k_nop<<<1, 32>>>();               // keeps ncu -s 5 aligned onto k_main
    k_main<<<4096, 128>>>(x, w_ct, out);
}

// round 15
// speedup vs baseline: 2.1176x; 1.1279x over previous
#include <cuda_runtime.h>
#include <cstdint>
#include <cstddef>

#define VIN  4096      // 16^3
#define VOUT 262144    // 64^3
#define PADP 36        // float2 row stride for paired x/w tables (72 floats ≡ 8 mod 32)
#define STGW 40        // staging row stride in floats (40 ≡ 8 mod 32 -> conflict-free)

// ---------------- device scratch (no allocation allowed) ----------------
__device__ float g_P1[512];   // partial sums: [nc*4+q]
__device__ float g_P2[512];
__device__ __align__(16) uint4 g_Frag[1024];   // [ks][mt][lane] A-fragments (tf32 bits), 16KB
__device__ float g_B[128];    // [n][o] fused bias
__device__ float g_rstd[2];

// ---------------- helpers ----------------
__device__ __forceinline__ uint32_t tf32_rna(float v) {
    uint32_t r;
    asm("cvt.rna.tf32.f32 %0, %1;" : "=r"(r) : "f"(v));
    return r;
}
__device__ __forceinline__ void mma_tf32(float* c, const uint32_t* a, uint32_t b0, uint32_t b1) {
    asm volatile(
        "mma.sync.aligned.m16n8k8.row.col.f32.tf32.tf32.f32 "
        "{%0,%1,%2,%3}, {%4,%5,%6,%7}, {%8,%9}, {%0,%1,%2,%3};"
        : "+f"(c[0]), "+f"(c[1]), "+f"(c[2]), "+f"(c[3])
        : "r"(a[0]), "r"(a[1]), "r"(a[2]), "r"(a[3]), "r"(b0), "r"(b1));
}
__device__ __forceinline__ void stcs1(float* p, float v) {
    asm volatile("st.global.cs.f32 [%0], %1;" :: "l"(p), "f"(v) : "memory");
}

// ---------------- kernel 0: dummy (ncu launch-index alignment) ----------------
__global__ void k_nop() {}

// ---------------- kernel 1: per-(n,c,quarter) partial sums ----------------
__global__ void __launch_bounds__(256)
k_stats(const float* __restrict__ x) {
    const int b = blockIdx.x;          // nc*4 + q
    const float4* p = (const float4*)(x + (size_t)b * 1024);
    float4 v = p[threadIdx.x];
    float a1 = v.x + v.y + v.z + v.w;
    float a2 = v.x * v.x + v.y * v.y + v.z * v.z + v.w * v.w;
#pragma unroll
    for (int off = 16; off; off >>= 1) {
        a1 += __shfl_xor_sync(0xffffffffu, a1, off);
        a2 += __shfl_xor_sync(0xffffffffu, a2, off);
    }
    __shared__ float s1[8], s2[8];
    int wid = threadIdx.x >> 5, lid = threadIdx.x & 31;
    if (lid == 0) { s1[wid] = a1; s2[wid] = a2; }
    __syncthreads();
    if (threadIdx.x == 0) {
        float t1 = 0.f, t2 = 0.f;
#pragma unroll
        for (int w = 0; w < 8; ++w) { t1 += s1[w]; t2 += s2[w]; }
        g_P1[b] = t1;
        g_P2[b] = t2;
    }
}

// ---------------- kernel 2: closed-form stats + fragment-ordered tf32 weights ----------------
__global__ void k_prep(const float* __restrict__ w_ct,
                       const float* __restrict__ b_ct,
                       const float* __restrict__ gamma,
                       const float* __restrict__ beta,
                       const float* __restrict__ w_pw) {
    __shared__ double dS1[128], dS2[128];
    __shared__ float sMean[2], sRstd[2];
    const int tid = threadIdx.x;

    if (tid < 128) {
        const int c = tid & 63;
        float s1 = 0.f, s2 = 0.f;
#pragma unroll 4
        for (int t = 0; t < 64; ++t) {
            float w = w_ct[c * 64 + t];
            s1 += w;
            s2 += w * w;
        }
        float X1 = g_P1[tid * 4] + g_P1[tid * 4 + 1] + g_P1[tid * 4 + 2] + g_P1[tid * 4 + 3];
        float X2 = g_P2[tid * 4] + g_P2[tid * 4 + 1] + g_P2[tid * 4 + 2] + g_P2[tid * 4 + 3];
        double bb = (double)b_ct[c];
        double S1 = (double)s1, S2 = (double)s2;
        dS1[tid] = S1 * (double)X1 + (double)VOUT * bb;
        dS2[tid] = S2 * (double)X2 + 2.0 * bb * S1 * (double)X1 + (double)VOUT * bb * bb;
    }
    __syncthreads();
#pragma unroll
    for (int st = 32; st > 0; st >>= 1) {
        if ((tid & 63) < st && tid < 128) {
            dS1[tid] += dS1[tid + st];
            dS2[tid] += dS2[tid + st];
        }
        __syncthreads();
    }
    if (tid < 2) {
        double sy = dS1[tid * 64], sy2 = dS2[tid * 64];
        double mean = sy / 16777216.0;
        double var  = sy2 / 16777216.0 - mean * mean;
        double rstd = 1.0 / sqrt(var + 1e-5);
        sMean[tid] = (float)mean;
        sRstd[tid] = (float)rstd;
        g_rstd[tid] = (float)rstd;
    }
    __syncthreads();

    // Fragment-ordered A: g_Frag[ks*4+mt][lane] = {Wg[o0][c0], Wg[o1][c0], Wg[o0][c1], Wg[o1][c1]}
    for (int idx = tid; idx < 1024; idx += 256) {
        const int ks = idx >> 7;
        const int mt = (idx >> 5) & 3;
        const int l = idx & 31;
        const int lq = l >> 2, lr = l & 3;
        const int o0 = mt * 16 + lq, o1 = o0 + 8;
        const int c0 = ks * 8 + lr, c1 = c0 + 4;
        uint4 f;
        f.x = tf32_rna(w_pw[o0 * 64 + c0] * gamma[c0]);
        f.y = tf32_rna(w_pw[o1 * 64 + c0] * gamma[c0]);
        f.z = tf32_rna(w_pw[o0 * 64 + c1] * gamma[c1]);
        f.w = tf32_rna(w_pw[o1 * 64 + c1] * gamma[c1]);
        g_Frag[idx] = f;
    }

    if (tid < 128) {
        int n = tid >> 6, o = tid & 63;
        float mean = sMean[n], rstd = sRstd[n];
        float acc1 = 0.f, acc2 = 0.f;
#pragma unroll 4
        for (int c = 0; c < 64; ++c) {
            float wpc = w_pw[o * 64 + c];
            acc1 += wpc * gamma[c] * (b_ct[c] - mean);
            acc2 += wpc * beta[c];
        }
        g_B[tid] = rstd * acc1 + acc2;
    }
}

// ---------------- kernel 3: tf32 HMMA scatter-GEMM, 64o x 64s warp tiles ----------------
// Block = (n, dout, h): 64 o x 256 s.  Warp w owns s in [w*64, w*64+64) -> j = w.
// s = j*64 + wout;  wout = nt*8 + lq;  w_in = wout>>2 = 2nt + (lq>>2);  k = lq&3.
// z[c][s] = w_ct[c, i, j, k] * x[n, c, d, h, w_in]
// out[n, o, dout, 4h + j, wout] = rstd * D + B[n][o]
__global__ void __launch_bounds__(128, 2)
k_main(const float* __restrict__ x,
       const float* __restrict__ w_ct,
       float* __restrict__ out) {
    __shared__ __align__(16) uint4 sFrag[1024];           // A fragments, 16 KB
    __shared__ __align__(16) float2 sXp[16 * PADP];       // [w_in][pair p]: (x[c], x[c+4])
    __shared__ __align__(16) float2 sWp[16 * PADP];       // [jk][pair p]
    __shared__ __align__(16) float sStage[4 * 16 * STGW]; // per-warp staging, 10.2 KB
    __shared__ float sB[64];

    const int tid = threadIdx.x;
    const int warp = tid >> 5;
    const int l = tid & 31;
    const int lq = l >> 2, lr = l & 3;

    const int b = blockIdx.x;
    const int n = b >> 10;
    const int dout = (b >> 4) & 63;
    const int h = b & 15;
    const int d = dout >> 2, i = dout & 3;

    // ---- stage operands ----
    {
#pragma unroll
        for (int t = 0; t < 8; ++t)
            sFrag[tid + t * 128] = g_Frag[tid + t * 128];
        float* xp = (float*)sXp;
        float* wp = (float*)sWp;
#pragma unroll
        for (int idx = tid; idx < 256; idx += 128) {
            const int c = idx >> 2, q = idx & 3;
            const int p2 = ((c >> 3) * 4 + (c & 3)) * 2 + ((c >> 2) & 1);  // float idx in row
            float4 xv = *(const float4*)(x + (size_t)(n * 64 + c) * VIN + d * 256 + h * 16 + q * 4);
            xp[(q * 4 + 0) * (2 * PADP) + p2] = xv.x;
            xp[(q * 4 + 1) * (2 * PADP) + p2] = xv.y;
            xp[(q * 4 + 2) * (2 * PADP) + p2] = xv.z;
            xp[(q * 4 + 3) * (2 * PADP) + p2] = xv.w;
            float4 wv = *(const float4*)(w_ct + c * 64 + i * 16 + q * 4);
            wp[(q * 4 + 0) * (2 * PADP) + p2] = wv.x;
            wp[(q * 4 + 1) * (2 * PADP) + p2] = wv.y;
            wp[(q * 4 + 2) * (2 * PADP) + p2] = wv.z;
            wp[(q * 4 + 3) * (2 * PADP) + p2] = wv.w;
        }
        if (tid < 64) sB[tid] = g_B[n * 64 + tid];
    }
    __syncthreads();

    const float rstd = g_rstd[n];

    // thread-constant w_ct row; x rows vary only with nt
    const int wrow = (warp * 4 + (lq & 3)) * PADP;
    const int xrhi = (lq >> 2);                    // 0/1: x row = 2*nt + xrhi

    float acc[4][8][4];
#pragma unroll
    for (int mt = 0; mt < 4; ++mt)
#pragma unroll
        for (int nt = 0; nt < 8; ++nt)
#pragma unroll
            for (int r = 0; r < 4; ++r) acc[mt][nt][r] = 0.f;

#pragma unroll
    for (int ks = 0; ks < 8; ++ks) {
        uint4 aV[4];
#pragma unroll
        for (int mt = 0; mt < 4; ++mt)
            aV[mt] = sFrag[(ks * 4 + mt) * 32 + l];
        const int p = ks * 4 + lr;
        const float2 wv = sWp[wrow + p];
#pragma unroll
        for (int nt = 0; nt < 8; ++nt) {
            float2 xv = sXp[(2 * nt + xrhi) * PADP + p];
            uint32_t b0 = tf32_rna(xv.x * wv.x);
            uint32_t b1 = tf32_rna(xv.y * wv.y);
#pragma unroll
            for (int mt = 0; mt < 4; ++mt)
                mma_tf32(acc[mt][nt], (const uint32_t*)&aV[mt], b0, b1);
        }
    }

    // ---- epilogue: per-warp smem-staged transpose -> coalesced streaming stores ----
    // hout = 4h + warp (j = warp), wout in [0,64)
    const size_t outBase = (size_t)n * 64 * VOUT + (size_t)dout * 4096
                         + (size_t)(4 * h + warp) * 64;
    float* stg = sStage + warp * (16 * STGW);

#pragma unroll
    for (int mt = 0; mt < 4; ++mt) {
        const int o0 = mt * 16 + lq;
        const int o1 = o0 + 8;
        const float B0 = sB[o0], B1 = sB[o1];
#pragma unroll
        for (int hh = 0; hh < 2; ++hh) {
            // write 4 n-tiles (32 s columns) into the staging buffer
#pragma unroll
            for (int t = 0; t < 4; ++t) {
                const int nt = hh * 4 + t;
                const int sl = t * 8 + 2 * lr;
                float2 v0, v1;
                v0.x = fmaf(rstd, acc[mt][nt][0], B0);
                v0.y = fmaf(rstd, acc[mt][nt][1], B0);
                v1.x = fmaf(rstd, acc[mt][nt][2], B1);
                v1.y = fmaf(rstd, acc[mt][nt][3], B1);
                *(float2*)&stg[lq * STGW + sl] = v0;
                *(float2*)&stg[(lq + 8) * STGW + sl] = v1;
            }
            __syncwarp();
            // read back rows, store 128B-coalesced
#pragma unroll
            for (int r = 0; r < 16; ++r) {
                float v = stg[r * STGW + l];
                const int o = mt * 16 + r;
                stcs1(out + outBase + (size_t)o * VOUT + hh * 32 + l, v);
            }
            __syncwarp();
        }
    }
}

extern "C" void kernel_launch(void* const* d_in, const int* in_sizes, int n_in,
                              void* d_out, int out_size) {
    (void)in_sizes; (void)n_in; (void)out_size;
    const float* x     = (const float*)d_in[0];
    const float* w_ct  = (const float*)d_in[1];
    const float* b_ct  = (const float*)d_in[2];
    const float* gamma = (const float*)d_in[3];
    const float* beta  = (const float*)d_in[4];
    const float* w_pw  = (const float*)d_in[5];
    float* out = (float*)d_out;

    k_stats<<<512, 256>>>(x);
    k_prep<<<1, 256>>>(w_ct, b_ct, gamma, beta, w_pw);
    k_nop<<<1, 32>>>();               // keeps ncu -s 5 aligned onto k_main
    k_main<<<2048, 128>>>(x, w_ct, out);
}